// round 9
// baseline (speedup 1.0000x reference)
#include <cuda_runtime.h>
typedef unsigned int u32;

#define Nn 65536
#define NK (Nn*16)
#define NTILES (Nn/8)
#define NT 512
#define GRID_MAIN 148

// ---- k_main float offsets in dynamic smem ----
#define F_ACT   0          // 128 x 132 A-tile (h, then px)
#define F_A1H   16896
#define F_A1L   18432
#define F_W1FH  19968
#define F_W1FL  20992
#define F_W2F   22016      // w2 frags
#define F_WSF   30208      // ws frags
#define F_PSM   46592      // 8 x 48
#define F_B2    46976
#define F_TOTAL 47040
#define SMEM_BYTES (F_TOTAL*4)

// ---- k_out float offsets ----
#define O_WOF 0            // 16K x 8n x 32 x 2 = 8192 floats
#define O_BO  8192
#define O_BNS 8256
#define O_BNQ 8320
#define O_FT  8384         // 128 x 132
#define O_TOTAL 25280
#define OSMEM_BYTES (O_TOTAL*4)
#define ONT 256

__device__ __forceinline__ float to_tf32(float x){
    float r; asm("cvt.rna.tf32.f32 %0, %1;":"=f"(r):"f"(x)); return r;
}
__device__ __forceinline__ void mma4(float* d, u32 a0, u32 a1, u32 a2, u32 a3,
                                     u32 b0, u32 b1){
    asm volatile("mma.sync.aligned.m16n8k8.row.col.f32.tf32.tf32.f32 "
        "{%0,%1,%2,%3}, {%4,%5,%6,%7}, {%8,%9}, {%0,%1,%2,%3};"
        : "+f"(d[0]),"+f"(d[1]),"+f"(d[2]),"+f"(d[3])
        : "r"(a0),"r"(a1),"r"(a2),"r"(a3),"r"(b0),"r"(b1));
}

// ---- scratch globals ----
__device__ float g_M1[10], g_M2[55], g_w1p[1280], g_c1[128];
__device__ float g_sum2[64], g_sumsq2[64], g_a2[64], g_c2[64];
__device__ float g_feat[(size_t)Nn*128];     // 32 MB pooled features

__global__ void k_zero(){
    int t = threadIdx.x;
    if (t < 10) g_M1[t]=0.f;
    if (t < 55) g_M2[t]=0.f;
    if (t < 64){ g_sum2[t]=0.f; g_sumsq2[t]=0.f; }
}

// ---- K1: concat moments, center-factored ----
__global__ void k_stats(const float* __restrict__ p){
    __shared__ float red[8][65];
    float m1[10], m2[55];
#pragma unroll
    for (int i=0;i<10;i++) m1[i]=0.f;
#pragma unroll
    for (int i=0;i<55;i++) m2[i]=0.f;

    int n = blockIdx.x*blockDim.x + threadIdx.x;
    {
        float4 pr[12];
        const float4* pp = (const float4*)(p + (size_t)n*48);
#pragma unroll
        for (int i=0;i<12;i++) pr[i] = pp[i];
        const float* pc = (const float*)pr;
        float C0=pc[0], C1=pc[1], C2=pc[2];
        float Sq0=0.f,Sq1=0.f,Sq2=0.f;
        float Q00=0.f,Q01=0.f,Q02=0.f,Q11=0.f,Q12=0.f,Q22=0.f;
        float Sd=0.f, Sdq0=0.f,Sdq1=0.f,Sdq2=0.f, Sdd=0.f;
#pragma unroll
        for (int k=0;k<16;k++){
            float qx=pc[3*k], qy=pc[3*k+1], qz=pc[3*k+2];
            float dx=C0-qx, dy=C1-qy, dz=C2-qz;
            float d2 = dx*dx + dy*dy + dz*dz;
            float ds = sqrtf(d2);
            Sq0+=qx; Sq1+=qy; Sq2+=qz;
            Q00=fmaf(qx,qx,Q00); Q01=fmaf(qx,qy,Q01); Q02=fmaf(qx,qz,Q02);
            Q11=fmaf(qy,qy,Q11); Q12=fmaf(qy,qz,Q12); Q22=fmaf(qz,qz,Q22);
            Sd+=ds; Sdq0=fmaf(ds,qx,Sdq0); Sdq1=fmaf(ds,qy,Sdq1); Sdq2=fmaf(ds,qz,Sdq2);
            Sdd+=d2;
        }
        float C[3]={C0,C1,C2};
        float Sq[3]={Sq0,Sq1,Sq2};
        float QQ[3][3]={{Q00,Q01,Q02},{Q01,Q11,Q12},{Q02,Q12,Q22}};
        float SDQ[3]={Sdq0,Sdq1,Sdq2};
#pragma unroll
        for (int i=0;i<3;i++){
            m1[i]   += 16.f*C[i];
            m1[3+i] += Sq[i];
            m1[6+i] += 16.f*C[i]-Sq[i];
        }
        m1[9] += Sd;
        int t = 0;
#pragma unroll
        for (int a=0;a<3;a++){
#pragma unroll
            for (int b=a;b<3;b++) m2[t++] += 16.f*C[a]*C[b];
#pragma unroll
            for (int b=0;b<3;b++) m2[t++] += C[a]*Sq[b];
#pragma unroll
            for (int b=0;b<3;b++) m2[t++] += C[a]*(16.f*C[b]-Sq[b]);
            m2[t++] += C[a]*Sd;
        }
#pragma unroll
        for (int a=0;a<3;a++){
#pragma unroll
            for (int b=a;b<3;b++) m2[t++] += QQ[a][b];
#pragma unroll
            for (int b=0;b<3;b++) m2[t++] += C[b]*Sq[a]-QQ[a][b];
            m2[t++] += SDQ[a];
        }
#pragma unroll
        for (int a=0;a<3;a++){
#pragma unroll
            for (int b=a;b<3;b++)
                m2[t++] += 16.f*C[a]*C[b]-C[a]*Sq[b]-C[b]*Sq[a]+QQ[a][b];
            m2[t++] += C[a]*Sd - SDQ[a];
        }
        m2[t++] += Sdd;
    }
#pragma unroll
    for (int off=16; off>0; off>>=1){
#pragma unroll
        for (int i=0;i<10;i++) m1[i] += __shfl_down_sync(0xffffffffu, m1[i], off);
#pragma unroll
        for (int i=0;i<55;i++) m2[i] += __shfl_down_sync(0xffffffffu, m2[i], off);
    }
    int wid = threadIdx.x>>5;
    if ((threadIdx.x&31)==0){
#pragma unroll
        for (int i=0;i<10;i++) red[wid][i]=m1[i];
#pragma unroll
        for (int i=0;i<55;i++) red[wid][10+i]=m2[i];
    }
    __syncthreads();
    if (threadIdx.x < 65){
        float a=0.f;
#pragma unroll
        for (int w=0;w<8;w++) a += red[w][threadIdx.x];
        if (threadIdx.x < 10) atomicAdd(&g_M1[threadIdx.x], a);
        else atomicAdd(&g_M2[threadIdx.x-10], a);
    }
}

__global__ void k_fold(const float* __restrict__ w1, const float* __restrict__ g1,
                       const float* __restrict__ be1){
    int d = threadIdx.x;
    const double invNK = 1.0/(double)NK;
    double wv[10];
#pragma unroll
    for (int c=0;c<10;c++) wv[c] = (double)w1[c*128+d];
    double m = 0.0;
#pragma unroll
    for (int c=0;c<10;c++) m += ((double)g_M1[c]*invNK)*wv[c];
    double q = 0.0; int t = 0;
#pragma unroll
    for (int a=0;a<10;a++)
#pragma unroll
        for (int b=a;b<10;b++){
            double s2 = (double)g_M2[t++]*invNK;
            double term = s2*wv[a]*wv[b];
            q += (a==b) ? term : 2.0*term;
        }
    double var = q - m*m;
    double a1 = (double)g1[d] / sqrt(var + 1e-5);
    g_c1[d] = (float)((double)be1[d] - m*a1);
#pragma unroll
    for (int c=0;c<10;c++) g_w1p[c*128+d] = (float)(wv[c]*a1);
}

__device__ __forceinline__ float w8row(int r, int c){
    switch(r){
        case 0: return g_w1p[384+c] - g_w1p[768+c];
        case 1: return g_w1p[512+c] - g_w1p[896+c];
        case 2: return g_w1p[640+c] - g_w1p[1024+c];
        case 3: return g_w1p[1152+c];
        case 4: return g_w1p[c]     + g_w1p[768+c];
        case 5: return g_w1p[128+c] + g_w1p[896+c];
        case 6: return g_w1p[256+c] + g_w1p[1024+c];
        default: return g_c1[c];
    }
}

__global__ void __launch_bounds__(NT,1) k_main(
    const float* __restrict__ p, const float* __restrict__ x,
    const float* __restrict__ w2, const float* __restrict__ b2,
    const float* __restrict__ ws)
{
    extern __shared__ float sm[];
    int tid = threadIdx.x, w = tid>>5, lid = tid&31;
    int g = lid>>2, tq = lid&3;
    int wl = w & 7;
    int rA = wl*16;
    bool lowhalf = (w < 8);
    int rg = w & 3, cg = w >> 2;
    int row0 = rg*32;

    // ---- stage weight fragments ----
    for (int i = tid; i < 2048; i += NT){
        int l2 = i&31, n2 = (i>>5)&3, K = i>>7;
        int g2 = l2>>2, t2 = l2&3;
        int r0 = K*8+t2, r1 = r0+4, c0 = n2*16+g2;
        float4 v;
        v.x = to_tf32(w2[r0*64+c0]);   v.y = to_tf32(w2[r1*64+c0]);
        v.z = to_tf32(w2[r0*64+c0+8]); v.w = to_tf32(w2[r1*64+c0+8]);
        *(float4*)&sm[F_W2F + i*4] = v;
    }
    for (int i = tid; i < 4096; i += NT){
        int l2 = i&31, n2 = (i>>5)&7, K = i>>8;
        int g2 = l2>>2, t2 = l2&3;
        int r0 = K*8+t2, r1 = r0+4, c0 = n2*16+g2;
        float4 v;
        v.x = to_tf32(ws[r0*128+c0]);   v.y = to_tf32(ws[r1*128+c0]);
        v.z = to_tf32(ws[r0*128+c0+8]); v.w = to_tf32(ws[r1*128+c0+8]);
        *(float4*)&sm[F_WSF + i*4] = v;
    }
    if (tid < 256){
        int i = tid, l2 = i&31, n2 = (i>>5)&7;
        int g2 = l2>>2, t2 = l2&3;
#pragma unroll
        for (int j=0;j<2;j++){
            int c = (2*n2+j)*8 + g2;
            float v0 = w8row(t2,   c);
            float v1 = w8row(t2+4, c);
            float h0 = to_tf32(v0), h1 = to_tf32(v1);
            sm[F_W1FH + (n2*32+l2)*4 + 2*j  ] = h0;
            sm[F_W1FH + (n2*32+l2)*4 + 2*j+1] = h1;
            sm[F_W1FL + (n2*32+l2)*4 + 2*j  ] = to_tf32(v0-h0);
            sm[F_W1FL + (n2*32+l2)*4 + 2*j+1] = to_tf32(v1-h1);
        }
    }
    if (tid < 64) sm[F_B2+tid]=b2[tid];
    __syncthreads();

    int xrow = wl*16 + (lid>>1);
    int xcol = (lowhalf?0:32) + (lid&1)*16;

    for (int t = blockIdx.x; t < NTILES; t += gridDim.x){
        const float4* xp = (const float4*)(x + ((size_t)t*128 + xrow)*64 + xcol);
        float4 xr[4];
#pragma unroll
        for (int i=0;i<4;i++) xr[i] = xp[i];

        if (tid < 96) *(float4*)&sm[F_PSM + tid*4] = *(const float4*)(p + (size_t)t*384 + tid*4);
        __syncthreads();

        if (tid < 128){
            int pt = tid>>4, k = tid&15;
            float cx=sm[F_PSM+pt*48],     cy=sm[F_PSM+pt*48+1],     cz=sm[F_PSM+pt*48+2];
            float qx=sm[F_PSM+pt*48+3*k], qy=sm[F_PSM+pt*48+3*k+1], qz=sm[F_PSM+pt*48+3*k+2];
            float dx=cx-qx, dy=cy-qy, dz=cz-qz;
            float ds = sqrtf(dx*dx+dy*dy+dz*dz);
            float vv[8] = {qx,qy,qz,ds,cx,cy,cz,1.f};
#pragma unroll
            for (int c=0;c<8;c++){
                float hi = to_tf32(vv[c]);
                sm[F_A1H + tid*12 + c] = hi;
                sm[F_A1L + tid*12 + c] = to_tf32(vv[c]-hi);
            }
        }
        __syncthreads();

        // ---- GEMM1 (K=8, split tf32): h = relu(A1 @ W8) ----
        {
            u32 ah0 = __float_as_uint(sm[F_A1H + (rA+g  )*12 + tq]);
            u32 ah1 = __float_as_uint(sm[F_A1H + (rA+g+8)*12 + tq]);
            u32 ah2 = __float_as_uint(sm[F_A1H + (rA+g  )*12 + tq+4]);
            u32 ah3 = __float_as_uint(sm[F_A1H + (rA+g+8)*12 + tq+4]);
            u32 al0 = __float_as_uint(sm[F_A1L + (rA+g  )*12 + tq]);
            u32 al1 = __float_as_uint(sm[F_A1L + (rA+g+8)*12 + tq]);
            u32 al2 = __float_as_uint(sm[F_A1L + (rA+g  )*12 + tq+4]);
            u32 al3 = __float_as_uint(sm[F_A1L + (rA+g+8)*12 + tq+4]);
            int n2b = lowhalf ? 0 : 4;
#pragma unroll
            for (int j=0;j<4;j++){
                int n2g = n2b + j;
                float4 bh = *(float4*)&sm[F_W1FH + (n2g*32+lid)*4];
                float4 bl = *(float4*)&sm[F_W1FL + (n2g*32+lid)*4];
#pragma unroll
                for (int par=0;par<2;par++){
                    float d[4] = {0.f,0.f,0.f,0.f};
                    u32 b0 = __float_as_uint(par? bh.z : bh.x);
                    u32 b1 = __float_as_uint(par? bh.w : bh.y);
                    u32 c0u= __float_as_uint(par? bl.z : bl.x);
                    u32 c1u= __float_as_uint(par? bl.w : bl.y);
                    mma4(d, ah0,ah1,ah2,ah3, b0,b1);
                    mma4(d, al0,al1,al2,al3, b0,b1);
                    mma4(d, ah0,ah1,ah2,ah3, c0u,c1u);
                    int c0 = (n2g*2+par)*8 + 2*tq;
                    float2 lo, hi;
                    lo.x = to_tf32(fmaxf(d[0],0.f)); lo.y = to_tf32(fmaxf(d[1],0.f));
                    hi.x = to_tf32(fmaxf(d[2],0.f)); hi.y = to_tf32(fmaxf(d[3],0.f));
                    *(float2*)&sm[F_ACT + (rA+g  )*132 + c0] = lo;
                    *(float2*)&sm[F_ACT + (rA+g+8)*132 + c0] = hi;
                }
            }
        }
        __syncthreads();

        // ---- GEMM2: p_c = h @ w2, register-double-buffered ----
        float d2[4][4];
#pragma unroll
        for (int n=0;n<4;n++){ d2[n][0]=0.f; d2[n][1]=0.f; d2[n][2]=0.f; d2[n][3]=0.f; }
        {
            int n2b = lowhalf ? 0 : 2;
            u32 aa[2][4]; float4 bb[2][2];
            {
                const float* ar = &sm[F_ACT + tq];
                aa[0][0]=__float_as_uint(ar[(rA+g  )*132]);
                aa[0][1]=__float_as_uint(ar[(rA+g+8)*132]);
                aa[0][2]=__float_as_uint(ar[(rA+g  )*132+4]);
                aa[0][3]=__float_as_uint(ar[(rA+g+8)*132+4]);
                bb[0][0]=*(float4*)&sm[F_W2F + ((n2b  )*32+lid)*4];
                bb[0][1]=*(float4*)&sm[F_W2F + ((n2b+1)*32+lid)*4];
            }
#pragma unroll
            for (int K=0;K<16;K++){
                int cur = K&1, nxt = cur^1;
                if (K < 15){
                    const float* ar = &sm[F_ACT + (K+1)*8 + tq];
                    aa[nxt][0]=__float_as_uint(ar[(rA+g  )*132]);
                    aa[nxt][1]=__float_as_uint(ar[(rA+g+8)*132]);
                    aa[nxt][2]=__float_as_uint(ar[(rA+g  )*132+4]);
                    aa[nxt][3]=__float_as_uint(ar[(rA+g+8)*132+4]);
                    bb[nxt][0]=*(float4*)&sm[F_W2F + (((K+1)*4+n2b  )*32+lid)*4];
                    bb[nxt][1]=*(float4*)&sm[F_W2F + (((K+1)*4+n2b+1)*32+lid)*4];
                }
                mma4(d2[0], aa[cur][0],aa[cur][1],aa[cur][2],aa[cur][3],
                     __float_as_uint(bb[cur][0].x), __float_as_uint(bb[cur][0].y));
                mma4(d2[1], aa[cur][0],aa[cur][1],aa[cur][2],aa[cur][3],
                     __float_as_uint(bb[cur][0].z), __float_as_uint(bb[cur][0].w));
                mma4(d2[2], aa[cur][0],aa[cur][1],aa[cur][2],aa[cur][3],
                     __float_as_uint(bb[cur][1].x), __float_as_uint(bb[cur][1].y));
                mma4(d2[3], aa[cur][0],aa[cur][1],aa[cur][2],aa[cur][3],
                     __float_as_uint(bb[cur][1].z), __float_as_uint(bb[cur][1].w));
            }
        }
        // write px = [p_c + b2 | x]
        {
            int nb = lowhalf ? 0 : 4;
#pragma unroll
            for (int n=0;n<4;n++){
                int c0 = (nb+n)*8 + 2*tq;
                float ba = sm[F_B2+c0], bb2 = sm[F_B2+c0+1];
                float2 lo, hi;
                lo.x = to_tf32(d2[n][0]+ba); lo.y = to_tf32(d2[n][1]+bb2);
                hi.x = to_tf32(d2[n][2]+ba); hi.y = to_tf32(d2[n][3]+bb2);
                *(float2*)&sm[F_ACT + (rA+g  )*132 + c0] = lo;
                *(float2*)&sm[F_ACT + (rA+g+8)*132 + c0] = hi;
            }
#pragma unroll
            for (int i=0;i<4;i++){
                float4 v = xr[i], wv;
                wv.x=to_tf32(v.x); wv.y=to_tf32(v.y); wv.z=to_tf32(v.z); wv.w=to_tf32(v.w);
                *(float4*)&sm[F_ACT + xrow*132 + 64 + xcol + i*4] = wv;
            }
        }
        __syncthreads();

        // ---- GEMM3: logits = px @ ws (mt=2, nt=4) ----
        float d3[2][4][4];
#pragma unroll
        for (int m=0;m<2;m++)
#pragma unroll
            for (int n=0;n<4;n++){ d3[m][n][0]=0.f; d3[m][n][1]=0.f; d3[m][n][2]=0.f; d3[m][n][3]=0.f; }
        {
#pragma unroll 4
            for (int K=0;K<16;K++){
                const float* ar = &sm[F_ACT + K*8 + tq];
                u32 a[2][4];
#pragma unroll
                for (int m=0;m<2;m++){
                    int rb = row0 + m*16;
                    a[m][0] = __float_as_uint(ar[(rb+g  )*132]);
                    a[m][1] = __float_as_uint(ar[(rb+g+8)*132]);
                    a[m][2] = __float_as_uint(ar[(rb+g  )*132+4]);
                    a[m][3] = __float_as_uint(ar[(rb+g+8)*132+4]);
                }
                float4 b0 = *(float4*)&sm[F_WSF + ((K*8 + 2*cg  )*32+lid)*4];
                float4 b1 = *(float4*)&sm[F_WSF + ((K*8 + 2*cg+1)*32+lid)*4];
#pragma unroll
                for (int m=0;m<2;m++){
                    mma4(d3[m][0], a[m][0],a[m][1],a[m][2],a[m][3], __float_as_uint(b0.x), __float_as_uint(b0.y));
                    mma4(d3[m][1], a[m][0],a[m][1],a[m][2],a[m][3], __float_as_uint(b0.z), __float_as_uint(b0.w));
                    mma4(d3[m][2], a[m][0],a[m][1],a[m][2],a[m][3], __float_as_uint(b1.x), __float_as_uint(b1.y));
                    mma4(d3[m][3], a[m][0],a[m][1],a[m][2],a[m][3], __float_as_uint(b1.z), __float_as_uint(b1.w));
                }
            }
        }

        // ---- softmax over k + pooled feat -> g_feat ----
#pragma unroll
        for (int m=0;m<2;m++){
            int pt = 2*rg + m;
            int rb = row0 + m*16;
#pragma unroll
            for (int nl=0; nl<4; nl++){
                int c0 = (4*cg+nl)*8 + 2*tq;
                float e0 = __expf(d3[m][nl][0]), e1 = __expf(d3[m][nl][1]);
                float e2 = __expf(d3[m][nl][2]), e3 = __expf(d3[m][nl][3]);
                float2 plo = *(float2*)&sm[F_ACT + (rb+g  )*132 + c0];
                float2 phi = *(float2*)&sm[F_ACT + (rb+g+8)*132 + c0];
                float se = e0+e2, so_ = e1+e3;
                float ve = fmaf(e0, plo.x, e2*phi.x);
                float vo = fmaf(e1, plo.y, e3*phi.y);
#pragma unroll
                for (int mm=4;mm<32;mm<<=1){
                    se += __shfl_xor_sync(0xffffffffu, se, mm);
                    so_ += __shfl_xor_sync(0xffffffffu, so_, mm);
                    ve += __shfl_xor_sync(0xffffffffu, ve, mm);
                    vo += __shfl_xor_sync(0xffffffffu, vo, mm);
                }
                if (lid < 4){
                    float2 f; f.x = ve/se; f.y = vo/so_;
                    *(float2*)&g_feat[((size_t)t*8 + pt)*128 + c0] = f;
                }
            }
        }
        __syncthreads();
    }
}

// ---- k_out: out = feat @ wo + bo, BN2 partials ----
__global__ void __launch_bounds__(ONT,1) k_out(const float* __restrict__ wo,
        const float* __restrict__ bo, float* __restrict__ out){
    extern __shared__ float so[];
    int tid = threadIdx.x, w = tid>>5, lid = tid&31;
    int g = lid>>2, tq = lid&3;
    for (int i = tid; i < 4096; i += ONT){      // FIXED: full 16 K-steps
        int l2 = i&31, n = (i>>5)&7, K = i>>8;
        int g2 = l2>>2, t2 = l2&3;
        float2 v;
        v.x = to_tf32(wo[(K*8+t2  )*64 + n*8+g2]);
        v.y = to_tf32(wo[(K*8+t2+4)*64 + n*8+g2]);
        *(float2*)&so[O_WOF + i*2] = v;
    }
    if (tid < 64){ so[O_BO+tid]=bo[tid]; so[O_BNS+tid]=0.f; so[O_BNQ+tid]=0.f; }
    {
        int row = tid>>1, ch = (tid&1)*64;
        const float4* fp = (const float4*)(g_feat + ((size_t)blockIdx.x*128 + row)*128 + ch);
#pragma unroll
        for (int i=0;i<16;i++)
            *(float4*)&so[O_FT + row*132 + ch + i*4] = fp[i];
    }
    __syncthreads();
    float d[8][4];
#pragma unroll
    for (int n=0;n<8;n++){ d[n][0]=0.f; d[n][1]=0.f; d[n][2]=0.f; d[n][3]=0.f; }
#pragma unroll 4
    for (int K=0;K<16;K++){
        const float* ar = &so[O_FT + (w*16)*132 + K*8 + tq];
        u32 a0 = __float_as_uint(ar[g*132]);
        u32 a1 = __float_as_uint(ar[(g+8)*132]);
        u32 a2 = __float_as_uint(ar[g*132+4]);
        u32 a3 = __float_as_uint(ar[(g+8)*132+4]);
#pragma unroll
        for (int n=0;n<8;n++){
            float2 bv = *(float2*)&so[O_WOF + ((K*8+n)*32+lid)*2];
            mma4(d[n], a0,a1,a2,a3, __float_as_uint(bv.x), __float_as_uint(bv.y));
        }
    }
    size_t rbase = (size_t)blockIdx.x*128 + w*16;
#pragma unroll
    for (int n=0;n<8;n++){
        int c0 = n*8 + 2*tq;
        float ba = so[O_BO+c0], bb = so[O_BO+c0+1];
        float v0 = d[n][0]+ba, v1 = d[n][1]+bb;
        float v2 = d[n][2]+ba, v3 = d[n][3]+bb;
        float2 lo, hi;
        lo.x=v0; lo.y=v1; hi.x=v2; hi.y=v3;
        *(float2*)&out[(rbase+g  )*64 + c0] = lo;
        *(float2*)&out[(rbase+g+8)*64 + c0] = hi;
        atomicAdd(&so[O_BNS+c0],   v0+v2);
        atomicAdd(&so[O_BNS+c0+1], v1+v3);
        atomicAdd(&so[O_BNQ+c0],   fmaf(v0,v0,v2*v2));
        atomicAdd(&so[O_BNQ+c0+1], fmaf(v1,v1,v3*v3));
    }
    __syncthreads();
    if (tid < 64){
        atomicAdd(&g_sum2[tid],   so[O_BNS+tid]);
        atomicAdd(&g_sumsq2[tid], so[O_BNQ+tid]);
    }
}

__global__ void k_fin(const float* __restrict__ g2, const float* __restrict__ be2){
    int j = threadIdx.x;
    double inv = 1.0/(double)Nn;
    double mu  = (double)g_sum2[j]*inv;
    double var = (double)g_sumsq2[j]*inv - mu*mu;
    double a2  = (double)g2[j] / sqrt(var + 1e-5);
    g_a2[j] = (float)a2;
    g_c2[j] = (float)((double)be2[j] - mu*a2);
}

__global__ void k_norm(float* __restrict__ out){
    __shared__ float a2s[64], c2s[64];
    if (threadIdx.x < 64){ a2s[threadIdx.x]=g_a2[threadIdx.x]; c2s[threadIdx.x]=g_c2[threadIdx.x]; }
    __syncthreads();
    const int nq = Nn*64/4;
    float4* o4 = (float4*)out;
    for (int f = blockIdx.x*blockDim.x + threadIdx.x; f < nq; f += gridDim.x*blockDim.x){
        float4 v = o4[f];
        int j = (f*4) & 63;
        v.x = fmaxf(fmaf(v.x, a2s[j],   c2s[j]),   0.f);
        v.y = fmaxf(fmaf(v.y, a2s[j+1], c2s[j+1]), 0.f);
        v.z = fmaxf(fmaf(v.z, a2s[j+2], c2s[j+2]), 0.f);
        v.w = fmaxf(fmaf(v.w, a2s[j+3], c2s[j+3]), 0.f);
        o4[f] = v;
    }
}

extern "C" void kernel_launch(void* const* d_in, const int* in_sizes, int n_in,
                              void* d_out, int out_size){
    const float* p   = (const float*)d_in[0];
    const float* x   = (const float*)d_in[1];
    const float* w1  = (const float*)d_in[2];
    const float* g1  = (const float*)d_in[4];
    const float* be1 = (const float*)d_in[5];
    const float* w2  = (const float*)d_in[6];
    const float* b2  = (const float*)d_in[7];
    const float* ws  = (const float*)d_in[8];
    const float* wo  = (const float*)d_in[9];
    const float* bo  = (const float*)d_in[10];
    const float* g2  = (const float*)d_in[11];
    const float* be2 = (const float*)d_in[12];
    float* out = (float*)d_out;
    (void)in_sizes; (void)n_in; (void)out_size;

    cudaFuncSetAttribute(k_main, cudaFuncAttributeMaxDynamicSharedMemorySize, SMEM_BYTES);
    cudaFuncSetAttribute(k_out,  cudaFuncAttributeMaxDynamicSharedMemorySize, OSMEM_BYTES);

    k_zero<<<1,64>>>();
    k_stats<<<256,256>>>(p);
    k_fold<<<1,128>>>(w1,g1,be1);
    k_main<<<GRID_MAIN,NT,SMEM_BYTES>>>(p,x,w2,b2,ws);
    k_out<<<Nn/128,ONT,OSMEM_BYTES>>>(wo,bo,out);
    k_fin<<<1,64>>>(g2,be2);
    k_norm<<<2048,256>>>(out);
}

// round 10
// speedup vs baseline: 1.0009x; 1.0009x over previous
#include <cuda_runtime.h>
typedef unsigned int u32;

#define Nn 65536
#define NK (Nn*16)
#define NTILES (Nn/8)
#define NT 512
#define GRID_MAIN 148

// ---- k_main float offsets in dynamic smem ----
#define F_ACT   0          // 128 x 132 A-tile (h, then px)
#define F_A1H   16896
#define F_A1L   18432
#define F_W1FH  19968
#define F_W1FL  20992
#define F_W2F   22016      // w2 frags
#define F_WSF   30208      // ws frags
#define F_PSM   46592      // 8 x 48
#define F_B2    46976
#define F_TOTAL 47040
#define SMEM_BYTES (F_TOTAL*4)

// ---- k_out float offsets ----
#define O_WOF 0            // 16K x 8n x 32 x 2 = 8192 floats
#define O_BO  8192
#define O_BNS 8256
#define O_BNQ 8320
#define O_FT  8384         // 128 x 132
#define O_TOTAL 25280
#define OSMEM_BYTES (O_TOTAL*4)
#define ONT 256

__device__ __forceinline__ float to_tf32(float x){
    float r; asm("cvt.rna.tf32.f32 %0, %1;":"=f"(r):"f"(x)); return r;
}
__device__ __forceinline__ void mma4(float* d, u32 a0, u32 a1, u32 a2, u32 a3,
                                     u32 b0, u32 b1){
    asm volatile("mma.sync.aligned.m16n8k8.row.col.f32.tf32.tf32.f32 "
        "{%0,%1,%2,%3}, {%4,%5,%6,%7}, {%8,%9}, {%0,%1,%2,%3};"
        : "+f"(d[0]),"+f"(d[1]),"+f"(d[2]),"+f"(d[3])
        : "r"(a0),"r"(a1),"r"(a2),"r"(a3),"r"(b0),"r"(b1));
}

// ---- scratch globals ----
__device__ float g_M1[10], g_M2[55], g_w1p[1280], g_c1[128];
__device__ float g_sum2[64], g_sumsq2[64], g_a2[64], g_c2[64];
__device__ float g_feat[(size_t)Nn*128];     // 32 MB pooled features

__global__ void k_zero(){
    int t = threadIdx.x;
    if (t < 10) g_M1[t]=0.f;
    if (t < 55) g_M2[t]=0.f;
    if (t < 64){ g_sum2[t]=0.f; g_sumsq2[t]=0.f; }
}

// ---- K1: concat moments, center-factored ----
__global__ void k_stats(const float* __restrict__ p){
    __shared__ float red[8][65];
    float m1[10], m2[55];
#pragma unroll
    for (int i=0;i<10;i++) m1[i]=0.f;
#pragma unroll
    for (int i=0;i<55;i++) m2[i]=0.f;

    int n = blockIdx.x*blockDim.x + threadIdx.x;
    {
        float4 pr[12];
        const float4* pp = (const float4*)(p + (size_t)n*48);
#pragma unroll
        for (int i=0;i<12;i++) pr[i] = pp[i];
        const float* pc = (const float*)pr;
        float C0=pc[0], C1=pc[1], C2=pc[2];
        float Sq0=0.f,Sq1=0.f,Sq2=0.f;
        float Q00=0.f,Q01=0.f,Q02=0.f,Q11=0.f,Q12=0.f,Q22=0.f;
        float Sd=0.f, Sdq0=0.f,Sdq1=0.f,Sdq2=0.f, Sdd=0.f;
#pragma unroll
        for (int k=0;k<16;k++){
            float qx=pc[3*k], qy=pc[3*k+1], qz=pc[3*k+2];
            float dx=C0-qx, dy=C1-qy, dz=C2-qz;
            float d2 = dx*dx + dy*dy + dz*dz;
            float ds = sqrtf(d2);
            Sq0+=qx; Sq1+=qy; Sq2+=qz;
            Q00=fmaf(qx,qx,Q00); Q01=fmaf(qx,qy,Q01); Q02=fmaf(qx,qz,Q02);
            Q11=fmaf(qy,qy,Q11); Q12=fmaf(qy,qz,Q12); Q22=fmaf(qz,qz,Q22);
            Sd+=ds; Sdq0=fmaf(ds,qx,Sdq0); Sdq1=fmaf(ds,qy,Sdq1); Sdq2=fmaf(ds,qz,Sdq2);
            Sdd+=d2;
        }
        float C[3]={C0,C1,C2};
        float Sq[3]={Sq0,Sq1,Sq2};
        float QQ[3][3]={{Q00,Q01,Q02},{Q01,Q11,Q12},{Q02,Q12,Q22}};
        float SDQ[3]={Sdq0,Sdq1,Sdq2};
#pragma unroll
        for (int i=0;i<3;i++){
            m1[i]   += 16.f*C[i];
            m1[3+i] += Sq[i];
            m1[6+i] += 16.f*C[i]-Sq[i];
        }
        m1[9] += Sd;
        int t = 0;
#pragma unroll
        for (int a=0;a<3;a++){
#pragma unroll
            for (int b=a;b<3;b++) m2[t++] += 16.f*C[a]*C[b];
#pragma unroll
            for (int b=0;b<3;b++) m2[t++] += C[a]*Sq[b];
#pragma unroll
            for (int b=0;b<3;b++) m2[t++] += C[a]*(16.f*C[b]-Sq[b]);
            m2[t++] += C[a]*Sd;
        }
#pragma unroll
        for (int a=0;a<3;a++){
#pragma unroll
            for (int b=a;b<3;b++) m2[t++] += QQ[a][b];
#pragma unroll
            for (int b=0;b<3;b++) m2[t++] += C[b]*Sq[a]-QQ[a][b];
            m2[t++] += SDQ[a];
        }
#pragma unroll
        for (int a=0;a<3;a++){
#pragma unroll
            for (int b=a;b<3;b++)
                m2[t++] += 16.f*C[a]*C[b]-C[a]*Sq[b]-C[b]*Sq[a]+QQ[a][b];
            m2[t++] += C[a]*Sd - SDQ[a];
        }
        m2[t++] += Sdd;
    }
#pragma unroll
    for (int off=16; off>0; off>>=1){
#pragma unroll
        for (int i=0;i<10;i++) m1[i] += __shfl_down_sync(0xffffffffu, m1[i], off);
#pragma unroll
        for (int i=0;i<55;i++) m2[i] += __shfl_down_sync(0xffffffffu, m2[i], off);
    }
    int wid = threadIdx.x>>5;
    if ((threadIdx.x&31)==0){
#pragma unroll
        for (int i=0;i<10;i++) red[wid][i]=m1[i];
#pragma unroll
        for (int i=0;i<55;i++) red[wid][10+i]=m2[i];
    }
    __syncthreads();
    if (threadIdx.x < 65){
        float a=0.f;
#pragma unroll
        for (int w=0;w<8;w++) a += red[w][threadIdx.x];
        if (threadIdx.x < 10) atomicAdd(&g_M1[threadIdx.x], a);
        else atomicAdd(&g_M2[threadIdx.x-10], a);
    }
}

__global__ void k_fold(const float* __restrict__ w1, const float* __restrict__ g1,
                       const float* __restrict__ be1){
    int d = threadIdx.x;
    const double invNK = 1.0/(double)NK;
    double wv[10];
#pragma unroll
    for (int c=0;c<10;c++) wv[c] = (double)w1[c*128+d];
    double m = 0.0;
#pragma unroll
    for (int c=0;c<10;c++) m += ((double)g_M1[c]*invNK)*wv[c];
    double q = 0.0; int t = 0;
#pragma unroll
    for (int a=0;a<10;a++)
#pragma unroll
        for (int b=a;b<10;b++){
            double s2 = (double)g_M2[t++]*invNK;
            double term = s2*wv[a]*wv[b];
            q += (a==b) ? term : 2.0*term;
        }
    double var = q - m*m;
    double a1 = (double)g1[d] / sqrt(var + 1e-5);
    g_c1[d] = (float)((double)be1[d] - m*a1);
#pragma unroll
    for (int c=0;c<10;c++) g_w1p[c*128+d] = (float)(wv[c]*a1);
}

__device__ __forceinline__ float w8row(int r, int c){
    switch(r){
        case 0: return g_w1p[384+c] - g_w1p[768+c];
        case 1: return g_w1p[512+c] - g_w1p[896+c];
        case 2: return g_w1p[640+c] - g_w1p[1024+c];
        case 3: return g_w1p[1152+c];
        case 4: return g_w1p[c]     + g_w1p[768+c];
        case 5: return g_w1p[128+c] + g_w1p[896+c];
        case 6: return g_w1p[256+c] + g_w1p[1024+c];
        default: return g_c1[c];
    }
}

__global__ void __launch_bounds__(NT,1) k_main(
    const float* __restrict__ p, const float* __restrict__ x,
    const float* __restrict__ w2, const float* __restrict__ b2,
    const float* __restrict__ ws)
{
    extern __shared__ float sm[];
    int tid = threadIdx.x, w = tid>>5, lid = tid&31;
    int g = lid>>2, tq = lid&3;
    int wl = w & 7;
    int rA = wl*16;
    bool lowhalf = (w < 8);
    int rg = w & 3, cg = w >> 2;
    int row0 = rg*32;

    // ---- stage weight fragments ----
    for (int i = tid; i < 2048; i += NT){
        int l2 = i&31, n2 = (i>>5)&3, K = i>>7;
        int g2 = l2>>2, t2 = l2&3;
        int r0 = K*8+t2, r1 = r0+4, c0 = n2*16+g2;
        float4 v;
        v.x = to_tf32(w2[r0*64+c0]);   v.y = to_tf32(w2[r1*64+c0]);
        v.z = to_tf32(w2[r0*64+c0+8]); v.w = to_tf32(w2[r1*64+c0+8]);
        *(float4*)&sm[F_W2F + i*4] = v;
    }
    for (int i = tid; i < 4096; i += NT){
        int l2 = i&31, n2 = (i>>5)&7, K = i>>8;
        int g2 = l2>>2, t2 = l2&3;
        int r0 = K*8+t2, r1 = r0+4, c0 = n2*16+g2;
        float4 v;
        v.x = to_tf32(ws[r0*128+c0]);   v.y = to_tf32(ws[r1*128+c0]);
        v.z = to_tf32(ws[r0*128+c0+8]); v.w = to_tf32(ws[r1*128+c0+8]);
        *(float4*)&sm[F_WSF + i*4] = v;
    }
    if (tid < 256){
        int i = tid, l2 = i&31, n2 = (i>>5)&7;
        int g2 = l2>>2, t2 = l2&3;
#pragma unroll
        for (int j=0;j<2;j++){
            int c = (2*n2+j)*8 + g2;
            float v0 = w8row(t2,   c);
            float v1 = w8row(t2+4, c);
            float h0 = to_tf32(v0), h1 = to_tf32(v1);
            sm[F_W1FH + (n2*32+l2)*4 + 2*j  ] = h0;
            sm[F_W1FH + (n2*32+l2)*4 + 2*j+1] = h1;
            sm[F_W1FL + (n2*32+l2)*4 + 2*j  ] = to_tf32(v0-h0);
            sm[F_W1FL + (n2*32+l2)*4 + 2*j+1] = to_tf32(v1-h1);
        }
    }
    if (tid < 64) sm[F_B2+tid]=b2[tid];
    __syncthreads();

    int xrow = wl*16 + (lid>>1);
    int xcol = (lowhalf?0:32) + (lid&1)*16;

    for (int t = blockIdx.x; t < NTILES; t += gridDim.x){
        const float4* xp = (const float4*)(x + ((size_t)t*128 + xrow)*64 + xcol);
        float4 xr[4];
#pragma unroll
        for (int i=0;i<4;i++) xr[i] = xp[i];

        if (tid < 96) *(float4*)&sm[F_PSM + tid*4] = *(const float4*)(p + (size_t)t*384 + tid*4);
        __syncthreads();

        if (tid < 128){
            int pt = tid>>4, k = tid&15;
            float cx=sm[F_PSM+pt*48],     cy=sm[F_PSM+pt*48+1],     cz=sm[F_PSM+pt*48+2];
            float qx=sm[F_PSM+pt*48+3*k], qy=sm[F_PSM+pt*48+3*k+1], qz=sm[F_PSM+pt*48+3*k+2];
            float dx=cx-qx, dy=cy-qy, dz=cz-qz;
            float ds = sqrtf(dx*dx+dy*dy+dz*dz);
            float vv[8] = {qx,qy,qz,ds,cx,cy,cz,1.f};
#pragma unroll
            for (int c=0;c<8;c++){
                float hi = to_tf32(vv[c]);
                sm[F_A1H + tid*12 + c] = hi;
                sm[F_A1L + tid*12 + c] = to_tf32(vv[c]-hi);
            }
        }
        __syncthreads();

        // ---- GEMM1 (K=8, split tf32): h = relu(A1 @ W8) ----
        {
            u32 ah0 = __float_as_uint(sm[F_A1H + (rA+g  )*12 + tq]);
            u32 ah1 = __float_as_uint(sm[F_A1H + (rA+g+8)*12 + tq]);
            u32 ah2 = __float_as_uint(sm[F_A1H + (rA+g  )*12 + tq+4]);
            u32 ah3 = __float_as_uint(sm[F_A1H + (rA+g+8)*12 + tq+4]);
            u32 al0 = __float_as_uint(sm[F_A1L + (rA+g  )*12 + tq]);
            u32 al1 = __float_as_uint(sm[F_A1L + (rA+g+8)*12 + tq]);
            u32 al2 = __float_as_uint(sm[F_A1L + (rA+g  )*12 + tq+4]);
            u32 al3 = __float_as_uint(sm[F_A1L + (rA+g+8)*12 + tq+4]);
            int n2b = lowhalf ? 0 : 4;
#pragma unroll
            for (int j=0;j<4;j++){
                int n2g = n2b + j;
                float4 bh = *(float4*)&sm[F_W1FH + (n2g*32+lid)*4];
                float4 bl = *(float4*)&sm[F_W1FL + (n2g*32+lid)*4];
#pragma unroll
                for (int par=0;par<2;par++){
                    float d[4] = {0.f,0.f,0.f,0.f};
                    u32 b0 = __float_as_uint(par? bh.z : bh.x);
                    u32 b1 = __float_as_uint(par? bh.w : bh.y);
                    u32 c0u= __float_as_uint(par? bl.z : bl.x);
                    u32 c1u= __float_as_uint(par? bl.w : bl.y);
                    mma4(d, ah0,ah1,ah2,ah3, b0,b1);
                    mma4(d, al0,al1,al2,al3, b0,b1);
                    mma4(d, ah0,ah1,ah2,ah3, c0u,c1u);
                    int c0 = (n2g*2+par)*8 + 2*tq;
                    float2 lo, hi;
                    lo.x = to_tf32(fmaxf(d[0],0.f)); lo.y = to_tf32(fmaxf(d[1],0.f));
                    hi.x = to_tf32(fmaxf(d[2],0.f)); hi.y = to_tf32(fmaxf(d[3],0.f));
                    *(float2*)&sm[F_ACT + (rA+g  )*132 + c0] = lo;
                    *(float2*)&sm[F_ACT + (rA+g+8)*132 + c0] = hi;
                }
            }
        }
        __syncthreads();

        // ---- GEMM2: p_c = h @ w2, register-double-buffered ----
        float d2[4][4];
#pragma unroll
        for (int n=0;n<4;n++){ d2[n][0]=0.f; d2[n][1]=0.f; d2[n][2]=0.f; d2[n][3]=0.f; }
        {
            int n2b = lowhalf ? 0 : 2;
            u32 aa[2][4]; float4 bb[2][2];
            {
                const float* ar = &sm[F_ACT + tq];
                aa[0][0]=__float_as_uint(ar[(rA+g  )*132]);
                aa[0][1]=__float_as_uint(ar[(rA+g+8)*132]);
                aa[0][2]=__float_as_uint(ar[(rA+g  )*132+4]);
                aa[0][3]=__float_as_uint(ar[(rA+g+8)*132+4]);
                bb[0][0]=*(float4*)&sm[F_W2F + ((n2b  )*32+lid)*4];
                bb[0][1]=*(float4*)&sm[F_W2F + ((n2b+1)*32+lid)*4];
            }
#pragma unroll
            for (int K=0;K<16;K++){
                int cur = K&1, nxt = cur^1;
                if (K < 15){
                    const float* ar = &sm[F_ACT + (K+1)*8 + tq];
                    aa[nxt][0]=__float_as_uint(ar[(rA+g  )*132]);
                    aa[nxt][1]=__float_as_uint(ar[(rA+g+8)*132]);
                    aa[nxt][2]=__float_as_uint(ar[(rA+g  )*132+4]);
                    aa[nxt][3]=__float_as_uint(ar[(rA+g+8)*132+4]);
                    bb[nxt][0]=*(float4*)&sm[F_W2F + (((K+1)*4+n2b  )*32+lid)*4];
                    bb[nxt][1]=*(float4*)&sm[F_W2F + (((K+1)*4+n2b+1)*32+lid)*4];
                }
                mma4(d2[0], aa[cur][0],aa[cur][1],aa[cur][2],aa[cur][3],
                     __float_as_uint(bb[cur][0].x), __float_as_uint(bb[cur][0].y));
                mma4(d2[1], aa[cur][0],aa[cur][1],aa[cur][2],aa[cur][3],
                     __float_as_uint(bb[cur][0].z), __float_as_uint(bb[cur][0].w));
                mma4(d2[2], aa[cur][0],aa[cur][1],aa[cur][2],aa[cur][3],
                     __float_as_uint(bb[cur][1].x), __float_as_uint(bb[cur][1].y));
                mma4(d2[3], aa[cur][0],aa[cur][1],aa[cur][2],aa[cur][3],
                     __float_as_uint(bb[cur][1].z), __float_as_uint(bb[cur][1].w));
            }
        }
        // write px = [p_c + b2 | x]
        {
            int nb = lowhalf ? 0 : 4;
#pragma unroll
            for (int n=0;n<4;n++){
                int c0 = (nb+n)*8 + 2*tq;
                float ba = sm[F_B2+c0], bb2 = sm[F_B2+c0+1];
                float2 lo, hi;
                lo.x = to_tf32(d2[n][0]+ba); lo.y = to_tf32(d2[n][1]+bb2);
                hi.x = to_tf32(d2[n][2]+ba); hi.y = to_tf32(d2[n][3]+bb2);
                *(float2*)&sm[F_ACT + (rA+g  )*132 + c0] = lo;
                *(float2*)&sm[F_ACT + (rA+g+8)*132 + c0] = hi;
            }
#pragma unroll
            for (int i=0;i<4;i++){
                float4 v = xr[i], wv;
                wv.x=to_tf32(v.x); wv.y=to_tf32(v.y); wv.z=to_tf32(v.z); wv.w=to_tf32(v.w);
                *(float4*)&sm[F_ACT + xrow*132 + 64 + xcol + i*4] = wv;
            }
        }
        __syncthreads();

        // ---- GEMM3: logits = px @ ws (mt=2, nt=4) ----
        float d3[2][4][4];
#pragma unroll
        for (int m=0;m<2;m++)
#pragma unroll
            for (int n=0;n<4;n++){ d3[m][n][0]=0.f; d3[m][n][1]=0.f; d3[m][n][2]=0.f; d3[m][n][3]=0.f; }
        {
#pragma unroll 4
            for (int K=0;K<16;K++){
                const float* ar = &sm[F_ACT + K*8 + tq];
                u32 a[2][4];
#pragma unroll
                for (int m=0;m<2;m++){
                    int rb = row0 + m*16;
                    a[m][0] = __float_as_uint(ar[(rb+g  )*132]);
                    a[m][1] = __float_as_uint(ar[(rb+g+8)*132]);
                    a[m][2] = __float_as_uint(ar[(rb+g  )*132+4]);
                    a[m][3] = __float_as_uint(ar[(rb+g+8)*132+4]);
                }
                float4 b0 = *(float4*)&sm[F_WSF + ((K*8 + 2*cg  )*32+lid)*4];
                float4 b1 = *(float4*)&sm[F_WSF + ((K*8 + 2*cg+1)*32+lid)*4];
#pragma unroll
                for (int m=0;m<2;m++){
                    mma4(d3[m][0], a[m][0],a[m][1],a[m][2],a[m][3], __float_as_uint(b0.x), __float_as_uint(b0.y));
                    mma4(d3[m][1], a[m][0],a[m][1],a[m][2],a[m][3], __float_as_uint(b0.z), __float_as_uint(b0.w));
                    mma4(d3[m][2], a[m][0],a[m][1],a[m][2],a[m][3], __float_as_uint(b1.x), __float_as_uint(b1.y));
                    mma4(d3[m][3], a[m][0],a[m][1],a[m][2],a[m][3], __float_as_uint(b1.z), __float_as_uint(b1.w));
                }
            }
        }

        // ---- softmax over k + pooled feat -> g_feat ----
#pragma unroll
        for (int m=0;m<2;m++){
            int pt = 2*rg + m;
            int rb = row0 + m*16;
#pragma unroll
            for (int nl=0; nl<4; nl++){
                int c0 = (4*cg+nl)*8 + 2*tq;
                float e0 = __expf(d3[m][nl][0]), e1 = __expf(d3[m][nl][1]);
                float e2 = __expf(d3[m][nl][2]), e3 = __expf(d3[m][nl][3]);
                float2 plo = *(float2*)&sm[F_ACT + (rb+g  )*132 + c0];
                float2 phi = *(float2*)&sm[F_ACT + (rb+g+8)*132 + c0];
                float se = e0+e2, so_ = e1+e3;
                float ve = fmaf(e0, plo.x, e2*phi.x);
                float vo = fmaf(e1, plo.y, e3*phi.y);
#pragma unroll
                for (int mm=4;mm<32;mm<<=1){
                    se += __shfl_xor_sync(0xffffffffu, se, mm);
                    so_ += __shfl_xor_sync(0xffffffffu, so_, mm);
                    ve += __shfl_xor_sync(0xffffffffu, ve, mm);
                    vo += __shfl_xor_sync(0xffffffffu, vo, mm);
                }
                if (lid < 4){
                    float2 f; f.x = ve/se; f.y = vo/so_;
                    *(float2*)&g_feat[((size_t)t*8 + pt)*128 + c0] = f;
                }
            }
        }
        __syncthreads();
    }
}

// ---- k_out: out = feat @ wo + bo, BN2 partials ----
__global__ void __launch_bounds__(ONT,1) k_out(const float* __restrict__ wo,
        const float* __restrict__ bo, float* __restrict__ out){
    extern __shared__ float so[];
    int tid = threadIdx.x, w = tid>>5, lid = tid&31;
    int g = lid>>2, tq = lid&3;
    for (int i = tid; i < 4096; i += ONT){      // FIXED: full 16 K-steps
        int l2 = i&31, n = (i>>5)&7, K = i>>8;
        int g2 = l2>>2, t2 = l2&3;
        float2 v;
        v.x = to_tf32(wo[(K*8+t2  )*64 + n*8+g2]);
        v.y = to_tf32(wo[(K*8+t2+4)*64 + n*8+g2]);
        *(float2*)&so[O_WOF + i*2] = v;
    }
    if (tid < 64){ so[O_BO+tid]=bo[tid]; so[O_BNS+tid]=0.f; so[O_BNQ+tid]=0.f; }
    {
        int row = tid>>1, ch = (tid&1)*64;
        const float4* fp = (const float4*)(g_feat + ((size_t)blockIdx.x*128 + row)*128 + ch);
#pragma unroll
        for (int i=0;i<16;i++)
            *(float4*)&so[O_FT + row*132 + ch + i*4] = fp[i];
    }
    __syncthreads();
    float d[8][4];
#pragma unroll
    for (int n=0;n<8;n++){ d[n][0]=0.f; d[n][1]=0.f; d[n][2]=0.f; d[n][3]=0.f; }
#pragma unroll 4
    for (int K=0;K<16;K++){
        const float* ar = &so[O_FT + (w*16)*132 + K*8 + tq];
        u32 a0 = __float_as_uint(ar[g*132]);
        u32 a1 = __float_as_uint(ar[(g+8)*132]);
        u32 a2 = __float_as_uint(ar[g*132+4]);
        u32 a3 = __float_as_uint(ar[(g+8)*132+4]);
#pragma unroll
        for (int n=0;n<8;n++){
            float2 bv = *(float2*)&so[O_WOF + ((K*8+n)*32+lid)*2];
            mma4(d[n], a0,a1,a2,a3, __float_as_uint(bv.x), __float_as_uint(bv.y));
        }
    }
    size_t rbase = (size_t)blockIdx.x*128 + w*16;
#pragma unroll
    for (int n=0;n<8;n++){
        int c0 = n*8 + 2*tq;
        float ba = so[O_BO+c0], bb = so[O_BO+c0+1];
        float v0 = d[n][0]+ba, v1 = d[n][1]+bb;
        float v2 = d[n][2]+ba, v3 = d[n][3]+bb;
        float2 lo, hi;
        lo.x=v0; lo.y=v1; hi.x=v2; hi.y=v3;
        *(float2*)&out[(rbase+g  )*64 + c0] = lo;
        *(float2*)&out[(rbase+g+8)*64 + c0] = hi;
        atomicAdd(&so[O_BNS+c0],   v0+v2);
        atomicAdd(&so[O_BNS+c0+1], v1+v3);
        atomicAdd(&so[O_BNQ+c0],   fmaf(v0,v0,v2*v2));
        atomicAdd(&so[O_BNQ+c0+1], fmaf(v1,v1,v3*v3));
    }
    __syncthreads();
    if (tid < 64){
        atomicAdd(&g_sum2[tid],   so[O_BNS+tid]);
        atomicAdd(&g_sumsq2[tid], so[O_BNQ+tid]);
    }
}

__global__ void k_fin(const float* __restrict__ g2, const float* __restrict__ be2){
    int j = threadIdx.x;
    double inv = 1.0/(double)Nn;
    double mu  = (double)g_sum2[j]*inv;
    double var = (double)g_sumsq2[j]*inv - mu*mu;
    double a2  = (double)g2[j] / sqrt(var + 1e-5);
    g_a2[j] = (float)a2;
    g_c2[j] = (float)((double)be2[j] - mu*a2);
}

__global__ void k_norm(float* __restrict__ out){
    __shared__ float a2s[64], c2s[64];
    if (threadIdx.x < 64){ a2s[threadIdx.x]=g_a2[threadIdx.x]; c2s[threadIdx.x]=g_c2[threadIdx.x]; }
    __syncthreads();
    const int nq = Nn*64/4;
    float4* o4 = (float4*)out;
    for (int f = blockIdx.x*blockDim.x + threadIdx.x; f < nq; f += gridDim.x*blockDim.x){
        float4 v = o4[f];
        int j = (f*4) & 63;
        v.x = fmaxf(fmaf(v.x, a2s[j],   c2s[j]),   0.f);
        v.y = fmaxf(fmaf(v.y, a2s[j+1], c2s[j+1]), 0.f);
        v.z = fmaxf(fmaf(v.z, a2s[j+2], c2s[j+2]), 0.f);
        v.w = fmaxf(fmaf(v.w, a2s[j+3], c2s[j+3]), 0.f);
        o4[f] = v;
    }
}

extern "C" void kernel_launch(void* const* d_in, const int* in_sizes, int n_in,
                              void* d_out, int out_size){
    const float* p   = (const float*)d_in[0];
    const float* x   = (const float*)d_in[1];
    const float* w1  = (const float*)d_in[2];
    const float* g1  = (const float*)d_in[4];
    const float* be1 = (const float*)d_in[5];
    const float* w2  = (const float*)d_in[6];
    const float* b2  = (const float*)d_in[7];
    const float* ws  = (const float*)d_in[8];
    const float* wo  = (const float*)d_in[9];
    const float* bo  = (const float*)d_in[10];
    const float* g2  = (const float*)d_in[11];
    const float* be2 = (const float*)d_in[12];
    float* out = (float*)d_out;
    (void)in_sizes; (void)n_in; (void)out_size;

    cudaFuncSetAttribute(k_main, cudaFuncAttributeMaxDynamicSharedMemorySize, SMEM_BYTES);
    cudaFuncSetAttribute(k_out,  cudaFuncAttributeMaxDynamicSharedMemorySize, OSMEM_BYTES);

    k_zero<<<1,64>>>();
    k_stats<<<256,256>>>(p);
    k_fold<<<1,128>>>(w1,g1,be1);
    k_main<<<GRID_MAIN,NT,SMEM_BYTES>>>(p,x,w2,b2,ws);
    k_out<<<Nn/128,ONT,OSMEM_BYTES>>>(wo,bo,out);
    k_fin<<<1,64>>>(g2,be2);
    k_norm<<<2048,256>>>(out);
}